// round 9
// baseline (speedup 1.0000x reference)
#include <cuda_runtime.h>
#include <cuda_bf16.h>
#include <cstdint>

constexpr int Bn = 4;
constexpr int Sn = 4096;
constexpr int Dn = 256;

// Device-global scratch (no cudaMalloc allowed)
__device__ float         g_V [(size_t)Bn * Sn * Dn];   // v = xW^T+b, fp32 (epilogue/diag)
__device__ float         g_Sq[(size_t)Bn * Sn];        // per-row ||x||^2 fp32
__device__ __nv_bfloat16 g_Xb[(size_t)Bn * Sn * Dn];   // x hi (bf16)
__device__ __nv_bfloat16 g_Xl[(size_t)Bn * Sn * Dn];   // x lo (bf16 of residual)
__device__ __nv_bfloat16 g_Vb[(size_t)Bn * Sn * Dn];   // V bf16, natural layout
__device__ __nv_bfloat16 g_Wh[Dn * Dn];                // W hi
__device__ __nv_bfloat16 g_Wl[Dn * Dn];                // W lo

// ============================ helpers ============================
__device__ __forceinline__ uint32_t smem_u32(const void* p) {
    uint32_t a;
    asm("{ .reg .u64 t; cvta.to.shared.u64 t, %1; cvt.u32.u64 %0, t; }" : "=r"(a) : "l"(p));
    return a;
}
__device__ __forceinline__ void ldsm_x4(uint32_t* r, uint32_t addr) {
    asm volatile("ldmatrix.sync.aligned.m8n8.x4.shared.b16 {%0,%1,%2,%3}, [%4];"
                 : "=r"(r[0]), "=r"(r[1]), "=r"(r[2]), "=r"(r[3]) : "r"(addr));
}
__device__ __forceinline__ void ldsm_x4t(uint32_t* r, uint32_t addr) {
    asm volatile("ldmatrix.sync.aligned.m8n8.x4.trans.shared.b16 {%0,%1,%2,%3}, [%4];"
                 : "=r"(r[0]), "=r"(r[1]), "=r"(r[2]), "=r"(r[3]) : "r"(addr));
}
__device__ __forceinline__ void mma16816(float* d, const uint32_t* a, const uint32_t* b) {
    asm volatile("mma.sync.aligned.m16n8k16.row.col.f32.bf16.bf16.f32 "
                 "{%0,%1,%2,%3}, {%4,%5,%6,%7}, {%8,%9}, {%0,%1,%2,%3};"
                 : "+f"(d[0]), "+f"(d[1]), "+f"(d[2]), "+f"(d[3])
                 : "r"(a[0]), "r"(a[1]), "r"(a[2]), "r"(a[3]), "r"(b[0]), "r"(b[1]));
}
#define CP16(dst, src) \
    asm volatile("cp.async.cg.shared.global [%0], [%1], 16;" :: "r"(dst), "l"(src))
#define CP_COMMIT() asm volatile("cp.async.commit_group;" ::: "memory")
#define CP_WAIT0()  asm volatile("cp.async.wait_group 0;" ::: "memory")

__device__ __forceinline__ uint32_t pack_bf2(float a, float b) {
    __nv_bfloat162 h = __floats2bfloat162_rn(a, b);
    return *reinterpret_cast<uint32_t*>(&h);
}

// ============================ K1: x -> bf16 hi/lo + ||x||^2 ============================
__global__ void k_prep(const float* __restrict__ x) {
    int row  = blockIdx.x * 8 + (threadIdx.x >> 5);
    int lane = threadIdx.x & 31;
    const float4* p = reinterpret_cast<const float4*>(x + (size_t)row * Dn) + lane * 2;
    float4 a = p[0], b = p[1];
    float v[8] = {a.x, a.y, a.z, a.w, b.x, b.y, b.z, b.w};
    float s = 0.f;
    uint32_t hi[4], lo[4];
#pragma unroll
    for (int i = 0; i < 4; ++i) {
        float v0 = v[2 * i], v1 = v[2 * i + 1];
        s = fmaf(v0, v0, s);
        s = fmaf(v1, v1, s);
        __nv_bfloat16 h0 = __float2bfloat16(v0);
        __nv_bfloat16 h1 = __float2bfloat16(v1);
        float l0 = v0 - __bfloat162float(h0);
        float l1 = v1 - __bfloat162float(h1);
        hi[i] = pack_bf2(__bfloat162float(h0), __bfloat162float(h1));
        lo[i] = pack_bf2(l0, l1);
    }
    *reinterpret_cast<uint4*>(g_Xb + (size_t)row * Dn + lane * 8) =
        make_uint4(hi[0], hi[1], hi[2], hi[3]);
    *reinterpret_cast<uint4*>(g_Xl + (size_t)row * Dn + lane * 8) =
        make_uint4(lo[0], lo[1], lo[2], lo[3]);
#pragma unroll
    for (int of = 16; of > 0; of >>= 1) s += __shfl_xor_sync(0xffffffffu, s, of);
    if (lane == 0) g_Sq[row] = s;
}

// ============================ K1b: W -> bf16 hi/lo ============================
__global__ void k_wprep(const float* __restrict__ W) {
    int i = blockIdx.x * 256 + threadIdx.x;     // 16384 threads x 4 floats
    float4 w = reinterpret_cast<const float4*>(W)[i];
    float v[4] = {w.x, w.y, w.z, w.w};
    uint32_t hi[2], lo[2];
#pragma unroll
    for (int q = 0; q < 2; ++q) {
        __nv_bfloat16 h0 = __float2bfloat16(v[2 * q]);
        __nv_bfloat16 h1 = __float2bfloat16(v[2 * q + 1]);
        hi[q] = pack_bf2(__bfloat162float(h0), __bfloat162float(h1));
        lo[q] = pack_bf2(v[2 * q] - __bfloat162float(h0), v[2 * q + 1] - __bfloat162float(h1));
    }
    *reinterpret_cast<uint2*>(g_Wh + (size_t)i * 4) = make_uint2(hi[0], hi[1]);
    *reinterpret_cast<uint2*>(g_Wl + (size_t)i * 4) = make_uint2(lo[0], lo[1]);
}

// ============================ K2: V = xW^T + b  (HMMA, hi/lo split) ============
constexpr int KV_XH = 0;                        // [128][72] bf16
constexpr int KV_XL = KV_XH + 128 * 72 * 2;     // 18432
constexpr int KV_WH = KV_XL + 128 * 72 * 2;     // 36864
constexpr int KV_WL = KV_WH + 64 * 72 * 2;      // 46080
constexpr int KV_SMEM = KV_WL + 64 * 72 * 2;    // 55296

__global__ __launch_bounds__(256) void k_v2(const float* __restrict__ bv) {
    extern __shared__ char smem[];
    const uint32_t sb = smem_u32(smem);
    const int tid  = threadIdx.x;
    const int w    = tid >> 5;
    const int lane = tid & 31;
    const int lq   = lane >> 2, lr = lane & 3;
    const int r0 = blockIdx.x * 128;            // flattened row
    const int c0 = blockIdx.y * 64;             // output col
    const int m0 = (w >> 1) * 32, n0 = (w & 1) * 32;

    float acc[2][4][4] = {};

    const uint32_t aXH = sb + KV_XH + (((m0 + (lane & 15)) * 72 + ((lane >> 4) << 3)) << 1);
    const uint32_t aXL = aXH + (KV_XL - KV_XH);
    const uint32_t aWH = sb + KV_WH + (((n0 + ((lane >> 4) << 3) + (lane & 7)) * 72
                                        + (((lane >> 3) & 1) << 3)) << 1);
    const uint32_t aWL = aWH + (KV_WL - KV_WH);

    for (int kc = 0; kc < 4; ++kc) {
        __syncthreads();
#pragma unroll
        for (int rep = 0; rep < 4; ++rep) {
            int u = tid + rep * 256;
            int r = u >> 3, cg = u & 7;
            *reinterpret_cast<uint4*>(smem + KV_XH + (r * 72 + cg * 8) * 2) =
                *reinterpret_cast<const uint4*>(g_Xb + (size_t)(r0 + r) * Dn + kc * 64 + cg * 8);
            *reinterpret_cast<uint4*>(smem + KV_XL + (r * 72 + cg * 8) * 2) =
                *reinterpret_cast<const uint4*>(g_Xl + (size_t)(r0 + r) * Dn + kc * 64 + cg * 8);
        }
#pragma unroll
        for (int rep = 0; rep < 2; ++rep) {
            int u = tid + rep * 256;
            int r = u >> 3, cg = u & 7;
            *reinterpret_cast<uint4*>(smem + KV_WH + (r * 72 + cg * 8) * 2) =
                *reinterpret_cast<const uint4*>(g_Wh + (size_t)(c0 + r) * Dn + kc * 64 + cg * 8);
            *reinterpret_cast<uint4*>(smem + KV_WL + (r * 72 + cg * 8) * 2) =
                *reinterpret_cast<const uint4*>(g_Wl + (size_t)(c0 + r) * Dn + kc * 64 + cg * 8);
        }
        __syncthreads();

#pragma unroll
        for (int ks = 0; ks < 4; ++ks) {
            const uint32_t ko = ks * 32;
            uint32_t AH[2][4], AL[2][4], BH[2][4], BL[2][4];
#pragma unroll
            for (int mt = 0; mt < 2; ++mt) {
                ldsm_x4(AH[mt], aXH + mt * (16 * 72 * 2) + ko);
                ldsm_x4(AL[mt], aXL + mt * (16 * 72 * 2) + ko);
            }
#pragma unroll
            for (int nt = 0; nt < 2; ++nt) {
                ldsm_x4(BH[nt], aWH + nt * (16 * 72 * 2) + ko);
                ldsm_x4(BL[nt], aWL + nt * (16 * 72 * 2) + ko);
            }
#pragma unroll
            for (int mt = 0; mt < 2; ++mt)
#pragma unroll
                for (int nt = 0; nt < 2; ++nt)
#pragma unroll
                    for (int nh = 0; nh < 2; ++nh) {
                        float* d = acc[mt][nt * 2 + nh];
                        mma16816(d, AH[mt], BH[nt] + nh * 2);
                        mma16816(d, AH[mt], BL[nt] + nh * 2);
                        mma16816(d, AL[mt], BH[nt] + nh * 2);
                    }
        }
    }

#pragma unroll
    for (int mt = 0; mt < 2; ++mt)
#pragma unroll
        for (int rr = 0; rr < 2; ++rr) {
            const int rg = r0 + m0 + mt * 16 + lq + rr * 8;
#pragma unroll
            for (int nn = 0; nn < 4; ++nn) {
                const int cg = c0 + n0 + nn * 8 + 2 * lr;
                float v0 = acc[mt][nn][rr * 2 + 0] + bv[cg];
                float v1 = acc[mt][nn][rr * 2 + 1] + bv[cg + 1];
                *reinterpret_cast<float2*>(g_V + (size_t)rg * Dn + cg) = make_float2(v0, v1);
                *reinterpret_cast<uint32_t*>(g_Vb + (size_t)rg * Dn + cg) = pack_bf2(v0, v1);
            }
        }
}

// ============================ K3: fused HMMA main kernel ====================
constexpr int XS_STR = 264;   // [128] rows
constexpr int XT_STR = 264;   // [64] rows, 2 buffers
constexpr int VB_STR = 264;   // [64] rows natural [t][d], 2 buffers
constexpr int P_STR  = 72;    // [128] rows

constexpr int OFF_RS = 0;                              // 512
constexpr int OFF_P  = 512;                            // 18432 -> 18944
constexpr int OFF_XS = 18944;                          // 67584 -> 86528
constexpr int OFF_XT = 86528;                          // 2 x 33792 -> 154112
constexpr int OFF_VB = 154112;                         // 2 x 33792 -> 221696
constexpr int XT_BUF = 64 * XT_STR * 2;                // 33792
constexpr int SMEM_MAIN = 221696;

// one phase-1 k-step: 3 ldsm + 4 mma into sacc
#define P1STEP() do {                                                   \
    uint32_t A_[4], B0_[4], B1_[4];                                     \
    ldsm_x4(A_, pa); ldsm_x4(B0_, pb0); ldsm_x4(B1_, pb1);              \
    mma16816(sacc[0], A_, B0_);                                         \
    mma16816(sacc[1], A_, B0_ + 2);                                     \
    mma16816(sacc[2], A_, B1_);                                         \
    mma16816(sacc[3], A_, B1_ + 2);                                     \
    pa += 32; pb0 += 32; pb1 += 32; } while (0)

__global__ __launch_bounds__(512, 1) void k_main(const float* __restrict__ logt,
                                                 float* __restrict__ out) {
    extern __shared__ char smem[];
    const uint32_t sb = smem_u32(smem);
    float* s_rs = reinterpret_cast<float*>(smem + OFF_RS);

    const int tid  = threadIdx.x;
    const int w    = tid >> 5;
    const int lane = tid & 31;
    const int lq   = lane >> 2, lr = lane & 3;

    const int bz = blockIdx.y;
    const int s0 = blockIdx.x * 128;
    const size_t base = (size_t)bz * Sn * Dn;
    const size_t bzS  = (size_t)bz * Sn;

    // phase-1 warp tile 16x32 (warps 8x2); phase-2 warp tile 32x64 (warps 4x4)
    const int m0  = (w >> 1) * 16, n0  = (w & 1) * 32;
    const int m0b = (w >> 2) * 32, n0b = (w & 3) * 64;

    if (tid < 128) s_rs[tid] = 0.f;

    // ---- prologue: async loads of XS + tile 0 ----
#pragma unroll
    for (int rep = 0; rep < 8; ++rep) {
        int u = tid + rep * 512;
        int r = u >> 5, cg = u & 31;
        CP16(sb + OFF_XS + (r * XS_STR + cg * 8) * 2,
             g_Xb + base + (size_t)(s0 + r) * Dn + cg * 8);
    }
#pragma unroll
    for (int rep = 0; rep < 4; ++rep) {
        int u = tid + rep * 512;
        int r = u >> 5, cg = u & 31;
        CP16(sb + OFF_XT + (r * XT_STR + cg * 8) * 2,
             g_Xb + base + (size_t)r * Dn + cg * 8);
        CP16(sb + OFF_VB + (r * VB_STR + cg * 8) * 2,
             g_Vb + base + (size_t)r * Dn + cg * 8);
    }
    CP_COMMIT();

    const float temp  = fmaxf(expf(logt[0]), 1e-5f);
    const float invT2 = __fdividef(1.f, temp * temp);

    const int ra = m0 + lq, rb = ra + 8;       // phase-1 rows owned by this lane
    const float sqA = g_Sq[bzS + s0 + ra];
    const float sqB = g_Sq[bzS + s0 + rb];

    // ldmatrix per-lane base addresses
    const uint32_t aA  = sb + OFF_XS + (((m0 + (lane & 15)) * XS_STR + ((lane >> 4) << 3)) << 1);
    const uint32_t aB0 = sb + OFF_XT + (((n0 + ((lane >> 4) << 3) + (lane & 7)) * XT_STR
                                         + (((lane >> 3) & 1) << 3)) << 1);
    const uint32_t aB1 = aB0 + 16 * XT_STR * 2;
    const uint32_t aP0 = sb + OFF_P + (((m0b + (lane & 15)) * P_STR + ((lane >> 4) << 3)) << 1);
    const uint32_t aP1 = aP0 + 16 * P_STR * 2;
    const uint32_t aVb = sb + OFF_VB + (((((lane >> 3) & 1) * 8 + (lane & 7)) * VB_STR
                                          + n0b + ((lane >> 4) << 3)) << 1);

    float dacc[2][8][4];
#pragma unroll
    for (int a = 0; a < 2; ++a)
#pragma unroll
        for (int b = 0; b < 8; ++b)
#pragma unroll
            for (int c = 0; c < 4; ++c) dacc[a][b][c] = 0.f;
    float rsA = 0.f, rsB = 0.f;
    float sacc[4][4];

    // elementwise: Cauchy + diag-zero + rowsum + bf16 pack -> P(t-tile)
    auto elementwise = [&](int t0_, const float2* t4_) {
#pragma unroll
        for (int fn = 0; fn < 4; ++fn) {
            const int c = n0 + fn * 8 + 2 * lr;
            const float sqt0 = t4_[fn].x;
            const float sqt1 = t4_[fn].y;
            float d00 = fmaxf(sqA + sqt0 - 2.f * sacc[fn][0], 0.f);
            float d01 = fmaxf(sqA + sqt1 - 2.f * sacc[fn][1], 0.f);
            float d10 = fmaxf(sqB + sqt0 - 2.f * sacc[fn][2], 0.f);
            float d11 = fmaxf(sqB + sqt1 - 2.f * sacc[fn][3], 0.f);
            float k00 = __fdividef(1.f, fmaf(d00, invT2, 1.f));
            float k01 = __fdividef(1.f, fmaf(d01, invT2, 1.f));
            float k10 = __fdividef(1.f, fmaf(d10, invT2, 1.f));
            float k11 = __fdividef(1.f, fmaf(d11, invT2, 1.f));
            if (s0 + ra == t0_ + c)     k00 = 0.f;
            if (s0 + ra == t0_ + c + 1) k01 = 0.f;
            if (s0 + rb == t0_ + c)     k10 = 0.f;
            if (s0 + rb == t0_ + c + 1) k11 = 0.f;
            rsA += k00 + k01;
            rsB += k10 + k11;
            *reinterpret_cast<uint32_t*>(smem + OFF_P + (ra * P_STR + c) * 2) = pack_bf2(k00, k01);
            *reinterpret_cast<uint32_t*>(smem + OFF_P + (rb * P_STR + c) * 2) = pack_bf2(k10, k11);
        }
    };

    // ================= peel iteration 0: phase1(0) + elementwise(0) =================
    {
        CP_WAIT0();
        __syncthreads();
        // prefetch tiles(1) -> buffer 1
#pragma unroll
        for (int rep = 0; rep < 4; ++rep) {
            int u = tid + rep * 512;
            int r = u >> 5, cg = u & 31;
            CP16(sb + OFF_XT + XT_BUF + (r * XT_STR + cg * 8) * 2,
                 g_Xb + base + (size_t)(64 + r) * Dn + cg * 8);
            CP16(sb + OFF_VB + XT_BUF + (r * VB_STR + cg * 8) * 2,
                 g_Vb + base + (size_t)(64 + r) * Dn + cg * 8);
        }
        CP_COMMIT();

        float2 t4[4];
#pragma unroll
        for (int fn = 0; fn < 4; ++fn)
            t4[fn] = *reinterpret_cast<const float2*>(g_Sq + bzS + n0 + fn * 8 + 2 * lr);

#pragma unroll
        for (int f = 0; f < 4; ++f)
#pragma unroll
            for (int c = 0; c < 4; ++c) sacc[f][c] = 0.f;
        uint32_t pa = aA, pb0 = aB0, pb1 = aB1;
#pragma unroll
        for (int ks = 0; ks < 16; ++ks) P1STEP();

        elementwise(0, t4);
    }

    // ================= main loop: merged phase2(jt-1) || phase1(jt) =================
    for (int jt = 1; jt < 64; ++jt) {
        const int t0 = jt * 64;
        const uint32_t bo = (uint32_t)(jt & 1) * XT_BUF;   // tiles(jt)
        const uint32_t bp = bo ^ XT_BUF;                   // tiles(jt-1)

        CP_WAIT0();
        __syncthreads();   // publishes P(jt-1) and tiles(jt)

        // prefetch ||x_t||^2 for elementwise(jt)
        float2 t4[4];
#pragma unroll
        for (int fn = 0; fn < 4; ++fn)
            t4[fn] = *reinterpret_cast<const float2*>(g_Sq + bzS + t0 + n0 + fn * 8 + 2 * lr);

        // ---- merged block ----
#pragma unroll
        for (int f = 0; f < 4; ++f)
#pragma unroll
            for (int c = 0; c < 4; ++c) sacc[f][c] = 0.f;
        {
            uint32_t pa = aA, pb0 = aB0 + bo, pb1 = aB1 + bo;
            uint32_t qa0 = aP0, qa1 = aP1, qv = aVb + bp;
#pragma unroll
            for (int u = 0; u < 4; ++u) {
                uint32_t A0[4], A1[4];
                ldsm_x4(A0, qa0);
                ldsm_x4(A1, qa1);
                qa0 += 32; qa1 += 32;
                P1STEP();
#pragma unroll
                for (int qq = 0; qq < 2; ++qq) {
                    uint32_t Bva[4], Bvb[4];
                    ldsm_x4t(Bva, qv + qq * 64);
                    ldsm_x4t(Bvb, qv + qq * 64 + 32);
                    P1STEP();
                    const int q0 = 2 * qq, q1 = 2 * qq + 1;
                    mma16816(dacc[0][q0 * 2 + 0], A0, Bva);
                    mma16816(dacc[1][q0 * 2 + 0], A1, Bva);
                    mma16816(dacc[0][q0 * 2 + 1], A0, Bva + 2);
                    mma16816(dacc[1][q0 * 2 + 1], A1, Bva + 2);
                    mma16816(dacc[0][q1 * 2 + 0], A0, Bvb);
                    mma16816(dacc[1][q1 * 2 + 0], A1, Bvb);
                    mma16816(dacc[0][q1 * 2 + 1], A0, Bvb + 2);
                    mma16816(dacc[1][q1 * 2 + 1], A1, Bvb + 2);
                }
                qv += 16 * VB_STR * 2;
            }
            // remaining 4 phase-1 k-steps
#pragma unroll
            for (int ks = 0; ks < 4; ++ks) P1STEP();
        }
        __syncthreads();   // tiles(jt-1) + P(jt-1) free

        // prefetch tiles(jt+1) into buffer bp
        if (jt < 63) {
            const int tn = t0 + 64;
#pragma unroll
            for (int rep = 0; rep < 4; ++rep) {
                int u = tid + rep * 512;
                int r = u >> 5, cg = u & 31;
                CP16(sb + OFF_XT + bp + (r * XT_STR + cg * 8) * 2,
                     g_Xb + base + (size_t)(tn + r) * Dn + cg * 8);
                CP16(sb + OFF_VB + bp + (r * VB_STR + cg * 8) * 2,
                     g_Vb + base + (size_t)(tn + r) * Dn + cg * 8);
            }
        }
        CP_COMMIT();

        elementwise(t0, t4);
    }

    // ================= epilogue phase2(63) =================
    __syncthreads();   // publish P(63)
    {
        uint32_t qa0 = aP0, qa1 = aP1;
        uint32_t qv = aVb + XT_BUF;    // tiles(63) in buffer 1
#pragma unroll
        for (int ks = 0; ks < 4; ++ks) {
            uint32_t A0[4], A1[4], Bv[4][4];
            ldsm_x4(A0, qa0);
            ldsm_x4(A1, qa1);
#pragma unroll
            for (int q = 0; q < 4; ++q) ldsm_x4t(Bv[q], qv + q * 32);
#pragma unroll
            for (int q = 0; q < 4; ++q) {
                mma16816(dacc[0][q * 2 + 0], A0, Bv[q]);
                mma16816(dacc[1][q * 2 + 0], A1, Bv[q]);
                mma16816(dacc[0][q * 2 + 1], A0, Bv[q] + 2);
                mma16816(dacc[1][q * 2 + 1], A1, Bv[q] + 2);
            }
            qa0 += 32; qa1 += 32;
            qv += 16 * VB_STR * 2;
        }
    }

    // ---- rowsum reduce ----
    __syncthreads();
    atomicAdd(&s_rs[ra], rsA);
    atomicAdd(&s_rs[rb], rsB);
    __syncthreads();

    // ---- epilogue: out = (D + v_row) / (rowsum + 1) ----
#pragma unroll
    for (int mi = 0; mi < 2; ++mi) {
        const int r0e = m0b + mi * 16 + lq;
        const int r1e = r0e + 8;
        const float invA = __fdividef(1.f, s_rs[r0e] + 1.f);
        const float invB = __fdividef(1.f, s_rs[r1e] + 1.f);
        const size_t go0 = (bzS + s0 + r0e) * Dn;
        const size_t go1 = (bzS + s0 + r1e) * Dn;
#pragma unroll
        for (int fn = 0; fn < 8; ++fn) {
            const int c = n0b + fn * 8 + 2 * lr;
            float2 v0 = *reinterpret_cast<const float2*>(g_V + go0 + c);
            float2 v1 = *reinterpret_cast<const float2*>(g_V + go1 + c);
            float2 o0, o1;
            o0.x = (dacc[mi][fn][0] + v0.x) * invA;
            o0.y = (dacc[mi][fn][1] + v0.y) * invA;
            o1.x = (dacc[mi][fn][2] + v1.x) * invB;
            o1.y = (dacc[mi][fn][3] + v1.y) * invB;
            *reinterpret_cast<float2*>(out + go0 + c) = o0;
            *reinterpret_cast<float2*>(out + go1 + c) = o1;
        }
    }
}

// ============================ launch ============================
extern "C" void kernel_launch(void* const* d_in, const int* in_sizes, int n_in,
                              void* d_out, int out_size) {
    const float* x    = (const float*)d_in[0];
    const float* W    = (const float*)d_in[1];
    const float* bv   = (const float*)d_in[2];
    const float* logt = (const float*)d_in[3];
    float* out = (float*)d_out;

    cudaFuncSetAttribute(k_v2,   cudaFuncAttributeMaxDynamicSharedMemorySize, KV_SMEM);
    cudaFuncSetAttribute(k_main, cudaFuncAttributeMaxDynamicSharedMemorySize, SMEM_MAIN);

    k_prep<<<(Bn * Sn) / 8, 256>>>(x);
    k_wprep<<<64, 256>>>(W);
    k_v2<<<dim3((Bn * Sn) / 128, Dn / 64), 256, KV_SMEM>>>(bv);
    k_main<<<dim3(Sn / 128, Bn), 512, SMEM_MAIN>>>(logt, out);
}